// round 12
// baseline (speedup 1.0000x reference)
#include <cuda_runtime.h>

#define NB 32
#define NL 2048
#define ND 768
#define NV 32000
#define SPLITS 32
#define LPS (NL / SPLITS)      // 64 tokens per split
#define ND4 (ND / 4)           // 192 float4 per token row
#define PF 8                   // tokens prefetched before the flag wait
#define NTOK 11                // ceil(2048 / 192) tokens per weight-CTA thread

// Scratch (static device globals; zero-initialized at module load)
__device__ float        g_weights[NB * NL];   // normalized weights (1/norm folded in)
__device__ unsigned int g_hist[NB * NV];      // per-row histogram (4 MB)
__device__ unsigned int g_flag[NB];           // weights-ready flag per batch
__device__ unsigned int g_done[NB];           // pool-CTA completion counter per batch

// -------- block reduce for 6 warps (192 threads) --------
__device__ __forceinline__ float block_reduce6(float v, float* red) {
    __syncthreads();
    int lane = threadIdx.x & 31;
    int wid  = threadIdx.x >> 5;
#pragma unroll
    for (int o = 16; o > 0; o >>= 1) v += __shfl_down_sync(0xffffffffu, v, o);
    if (lane == 0) red[wid] = v;
    __syncthreads();
    if (wid == 0) {
        v = (lane < 6) ? red[lane] : 0.0f;
#pragma unroll
        for (int o = 16; o > 0; o >>= 1) v += __shfl_down_sync(0xffffffffu, v, o);
        if (lane == 0) red[0] = v;
    }
    __syncthreads();
    return red[0];
}

__global__ void __launch_bounds__(192) fused_kernel(
    const float* __restrict__ hid,
    const int*   __restrict__ mask,
    const int*   __restrict__ ids,      // int32 (JAX x64-disabled downgrades int64)
    const float* __restrict__ idf,
    const float* __restrict__ alphap,
    float*       __restrict__ out)
{
    __shared__ float w[LPS];      // pool: weight slab
    __shared__ float red[8];      // weights: reduce scratch

    const int tid = threadIdx.x;

    if (blockIdx.x < NB) {
        // ================= weight CTA for batch row b =================
        const int b = blockIdx.x;

        // zero d_out row (pool accumulates atomically after the flag)
#pragma unroll
        for (int i = 0; i < 4; i++) out[b * ND + tid + i * 192] = 0.0f;

        // zero this row's global histogram (8000 uint4)
        {
            uint4 z = make_uint4(0u, 0u, 0u, 0u);
            uint4* h4 = (uint4*)&g_hist[b * NV];
            for (int i = tid; i < NV / 4; i += 192) h4[i] = z;
        }
        __syncthreads();

        // load tokens, build histogram with global atomics
        int   tm[NTOK], ti[NTOK];
        float nv_loc = 0.0f;
#pragma unroll
        for (int i = 0; i < NTOK; i++) {
            int t = tid + i * 192;
            int m = 0, id = 0;
            if (t < NL) {
                m  = mask[b * NL + t];
                id = ids[b * NL + t];
                if ((unsigned)id >= (unsigned)NV) { id = 0; m = 0; }
                if (m) { atomicAdd(&g_hist[b * NV + id], 1u); nv_loc += 1.0f; }
            }
            tm[i] = m; ti[i] = id;
        }
        __threadfence();          // make this thread's atomics visible
        __syncthreads();          // all threads' atomics done + fenced

        const float n_valid = block_reduce6(nv_loc, red);
        const float inv_n   = 1.0f / fmaxf(n_valid, 1.0f);
        const float alpha   = *alphap;

        float wt[NTOK];
        float ws_loc = 0.0f;
#pragma unroll
        for (int i = 0; i < NTOK; i++) {
            float wv = 0.0f;
            int t = tid + i * 192;
            if (t < NL && tm[i]) {
                float c = (float)__ldcg(&g_hist[b * NV + ti[i]]);
                wv = 1.0f + alpha * (c * inv_n) * idf[ti[i]];
            }
            wt[i] = wv;
            ws_loc += wv;
        }
        const float wsum = block_reduce6(ws_loc, red);
        const float inv_norm = 1.0f / fmaxf(wsum, 1e-12f);

#pragma unroll
        for (int i = 0; i < NTOK; i++) {
            int t = tid + i * 192;
            if (t < NL) g_weights[b * NL + t] = wt[i] * inv_norm;
        }
        __threadfence();          // weights + out-zeros visible before flag
        __syncthreads();
        if (tid == 0) atomicExch(&g_flag[b], 1u);
    } else {
        // ================= pool CTA =================
        const int u = blockIdx.x - NB;
        const int s = u & (SPLITS - 1);
        const int b = u >> 5;     // SPLITS == 32

        const float4* base = (const float4*)hid
                           + ((size_t)b * NL + (size_t)s * LPS) * ND4 + tid;

        // prefetch first PF tokens while weights are being computed
        float4 r0 = base[0 * ND4];
        float4 r1 = base[1 * ND4];
        float4 r2 = base[2 * ND4];
        float4 r3 = base[3 * ND4];
        float4 r4 = base[4 * ND4];
        float4 r5 = base[5 * ND4];
        float4 r6 = base[6 * ND4];
        float4 r7 = base[7 * ND4];

        // wait for this batch's weights
        if (tid == 0) {
            volatile unsigned int* f = &g_flag[b];
            while (*f == 0u) __nanosleep(128);
        }
        __syncthreads();

        if (tid < LPS) w[tid] = __ldcg(&g_weights[b * NL + s * LPS + tid]);
        __syncthreads();

        float4 acc;
        acc.x = r0.x * w[0] + r1.x * w[1] + r2.x * w[2] + r3.x * w[3]
              + r4.x * w[4] + r5.x * w[5] + r6.x * w[6] + r7.x * w[7];
        acc.y = r0.y * w[0] + r1.y * w[1] + r2.y * w[2] + r3.y * w[3]
              + r4.y * w[4] + r5.y * w[5] + r6.y * w[6] + r7.y * w[7];
        acc.z = r0.z * w[0] + r1.z * w[1] + r2.z * w[2] + r3.z * w[3]
              + r4.z * w[4] + r5.z * w[5] + r6.z * w[6] + r7.z * w[7];
        acc.w = r0.w * w[0] + r1.w * w[1] + r2.w * w[2] + r3.w * w[3]
              + r4.w * w[4] + r5.w * w[5] + r6.w * w[6] + r7.w * w[7];

#pragma unroll 8
        for (int l = PF; l < LPS; l++) {
            float4 v = base[(size_t)l * ND4];
            float wl = w[l];
            acc.x += v.x * wl;
            acc.y += v.y * wl;
            acc.z += v.z * wl;
            acc.w += v.w * wl;
        }

        float* o = out + (size_t)b * ND + tid * 4;
        atomicAdd(o + 0, acc.x);
        atomicAdd(o + 1, acc.y);
        atomicAdd(o + 2, acc.z);
        atomicAdd(o + 3, acc.w);

        // self-reset handshake for the next graph replay
        __syncthreads();
        if (tid == 0) {
            unsigned int v = atomicAdd(&g_done[b], 1u);
            if (v == SPLITS - 1) {
                g_done[b] = 0u;
                g_flag[b] = 0u;
                __threadfence();
            }
        }
    }
}

extern "C" void kernel_launch(void* const* d_in, const int* in_sizes, int n_in,
                              void* d_out, int out_size)
{
    const float* hid   = (const float*)d_in[0];
    const int*   mask  = (const int*)d_in[1];
    const int*   ids   = (const int*)d_in[2];
    const float* idf   = (const float*)d_in[3];
    const float* alpha = (const float*)d_in[4];
    float*       out   = (float*)d_out;

    fused_kernel<<<NB + NB * SPLITS, 192>>>(hid, mask, ids, idf, alpha, out);
}

// round 14
// speedup vs baseline: 1.1950x; 1.1950x over previous
#include <cuda_runtime.h>
#include <cstdint>

#define NB 32
#define NL 2048
#define ND 768
#define NV 32000
#define SPLITS 32
#define LPS (NL / SPLITS)      // 64 tokens per split
#define ND4 (ND / 4)           // 192 float4 per token row
#define PF 8                   // tokens prefetched into SMEM before the PDL wait

// Scratch (no device allocation allowed in kernel_launch)
__device__ float g_weights[NB * NL];   // normalized weights (1/norm folded in)

// -------- block reduce (1024 threads = 32 warps) --------
__device__ __forceinline__ float block_reduce_sum(float v, float* red) {
    __syncthreads();  // protect red[] reuse across consecutive calls
    int lane = threadIdx.x & 31;
    int wid  = threadIdx.x >> 5;
#pragma unroll
    for (int o = 16; o > 0; o >>= 1) v += __shfl_down_sync(0xffffffffu, v, o);
    if (lane == 0) red[wid] = v;
    __syncthreads();
    if (wid == 0) {
        v = (lane < (int)(blockDim.x >> 5)) ? red[lane] : 0.0f;
#pragma unroll
        for (int o = 16; o > 0; o >>= 1) v += __shfl_down_sync(0xffffffffu, v, o);
        if (lane == 0) red[0] = v;
    }
    __syncthreads();
    return red[0];
}

// -------- kernel 1: per-row histogram -> normalized weights, zero d_out --------
// one CTA per batch row; dynamic SMEM = NV u32 hist + 32 f32 reduce scratch
__global__ void __launch_bounds__(1024) weights_kernel(
    const int* __restrict__ mask,
    const int* __restrict__ ids,      // int32 (JAX x64-disabled downgrades int64)
    const float* __restrict__ idf,
    const float* __restrict__ alphap,
    float* __restrict__ out)
{
    extern __shared__ unsigned char smraw[];
    unsigned int* hist = (unsigned int*)smraw;
    float* red = (float*)(hist + NV);

    const int b   = blockIdx.x;
    const int tid = threadIdx.x;

    // zero d_out row for this batch (pool kernel accumulates atomically)
    if (tid < ND) out[b * ND + tid] = 0.0f;

    // zero histogram with 16B stores: 32000 u32 = 8000 uint4
    {
        uint4 z = make_uint4(0u, 0u, 0u, 0u);
        uint4* h4 = (uint4*)hist;
#pragma unroll
        for (int i = 0; i < NV / 4 / 1024 + 1; i++) {
            int idx = tid + i * 1024;
            if (idx < NV / 4) h4[idx] = z;
        }
    }
    __syncthreads();

    // each thread owns 2 tokens (2048 / 1024)
    const int l0 = b * NL + tid;
    const int l1 = l0 + 1024;
    const int m0 = mask[l0];
    const int m1 = mask[l1];
    int id0 = ids[l0];
    int id1 = ids[l1];
    const int ok0 = ((unsigned)id0 < (unsigned)NV);
    const int ok1 = ((unsigned)id1 < (unsigned)NV);
    id0 = ok0 ? id0 : 0;
    id1 = ok1 ? id1 : 0;

    float nv_loc = 0.0f;
    if (m0 && ok0) { atomicAdd(&hist[id0], 1u); nv_loc += 1.0f; }
    if (m1 && ok1) { atomicAdd(&hist[id1], 1u); nv_loc += 1.0f; }
    __syncthreads();  // histogram complete

    const float n_valid = block_reduce_sum(nv_loc, red);
    const float inv_n   = 1.0f / fmaxf(n_valid, 1.0f);
    const float alpha   = *alphap;

    float w0 = 0.0f, w1 = 0.0f;
    if (m0 && ok0) w0 = 1.0f + alpha * ((float)hist[id0] * inv_n) * idf[id0];
    if (m1 && ok1) w1 = 1.0f + alpha * ((float)hist[id1] * inv_n) * idf[id1];

    const float wsum = block_reduce_sum(w0 + w1, red);
    const float inv_norm = 1.0f / fmaxf(wsum, 1e-12f);

    g_weights[l0] = w0 * inv_norm;
    g_weights[l1] = w1 * inv_norm;
}

// -------- kernel 2: streaming weighted sum (PDL secondary) --------
// grid = (SPLITS, NB), 192 threads; cp.async-prefetches PF tokens into SMEM
// BEFORE griddepcontrol.wait, so hid streaming overlaps the weights kernel.
__global__ void __launch_bounds__(192) pool_kernel(
    const float* __restrict__ hid,
    float* __restrict__ out)
{
    __shared__ float  w[LPS];
    __shared__ float4 pf[PF * 192];

    const int s = blockIdx.x;
    const int b = blockIdx.y;
    const int tid = threadIdx.x;

    const float4* base = (const float4*)hid + ((size_t)b * NL + (size_t)s * LPS) * ND4 + tid;

    // async prefetch of the first PF tokens (independent of weights)
#pragma unroll
    for (int l = 0; l < PF; l++) {
        uint32_t saddr = (uint32_t)__cvta_generic_to_shared(&pf[l * 192 + tid]);
        const void* src = (const void*)(base + (size_t)l * ND4);
        asm volatile("cp.async.cg.shared.global [%0], [%1], 16;\n" :: "r"(saddr), "l"(src));
    }
    asm volatile("cp.async.commit_group;\n" ::: "memory");

    // wait for the weights kernel's results (PDL)
    asm volatile("griddepcontrol.wait;\n" ::: "memory");

    if (tid < LPS) w[tid] = g_weights[b * NL + s * LPS + tid];
    asm volatile("cp.async.wait_group 0;\n" ::: "memory");
    __syncthreads();

    float4 acc = make_float4(0.f, 0.f, 0.f, 0.f);
#pragma unroll
    for (int l = 0; l < PF; l++) {
        float4 v = pf[l * 192 + tid];
        float wl = w[l];
        acc.x += v.x * wl;
        acc.y += v.y * wl;
        acc.z += v.z * wl;
        acc.w += v.w * wl;
    }

#pragma unroll 8
    for (int l = PF; l < LPS; l++) {
        float4 v = base[(size_t)l * ND4];
        float wl = w[l];
        acc.x += v.x * wl;
        acc.y += v.y * wl;
        acc.z += v.z * wl;
        acc.w += v.w * wl;
    }

    float* o = out + (size_t)b * ND + tid * 4;
    atomicAdd(o + 0, acc.x);
    atomicAdd(o + 1, acc.y);
    atomicAdd(o + 2, acc.z);
    atomicAdd(o + 3, acc.w);
}

extern "C" void kernel_launch(void* const* d_in, const int* in_sizes, int n_in,
                              void* d_out, int out_size)
{
    const float* hid   = (const float*)d_in[0];
    const int*   mask  = (const int*)d_in[1];
    const int*   ids   = (const int*)d_in[2];
    const float* idf   = (const float*)d_in[3];
    const float* alpha = (const float*)d_in[4];
    float*       out   = (float*)d_out;

    const int smem = NV * sizeof(unsigned int) + 32 * sizeof(float);
    cudaFuncSetAttribute(weights_kernel,
                         cudaFuncAttributeMaxDynamicSharedMemorySize, smem);

    weights_kernel<<<NB, 1024, smem>>>(mask, ids, idf, alpha, out);

    // pool as programmatic-dependent launch: CTAs start during weights_kernel,
    // prefetch hid, then griddepcontrol.wait gates use of g_weights / out.
    cudaLaunchConfig_t cfg = {};
    cfg.gridDim  = dim3(SPLITS, NB);
    cfg.blockDim = dim3(192);
    cfg.dynamicSmemBytes = 0;
    cfg.stream = 0;
    cudaLaunchAttribute attr[1];
    attr[0].id = cudaLaunchAttributeProgrammaticStreamSerialization;
    attr[0].val.programmaticStreamSerializationAllowed = 1;
    cfg.attrs = attr;
    cfg.numAttrs = 1;
    cudaLaunchKernelEx(&cfg, pool_kernel, hid, out);
}